// round 5
// baseline (speedup 1.0000x reference)
#include <cuda_runtime.h>
#include <cuda_bf16.h>
#include <math.h>

// ---------------- problem constants ----------------
#define Bn 8
#define Hn 192
#define Wn 192
#define Cn 64
#define NPIX (Bn*Hn*Wn)          // 294912
#define CV 81
#define CIN0 209
#define P0 216                    // padded channel stride (27 * 8)
#define FLOW_SCALE 271.52900393598527f
#define BN_EPS 1e-3f

// ---------------- scratch ----------------
__device__ float g_bufA[(size_t)NPIX * P0];
__device__ float g_bufB[(size_t)NPIX * 128];
__device__ float g_dw0pad[9 * P0];
__device__ float g_pw0pad[P0 * 128];

__device__ __forceinline__ float mish(float x) {
    float sp = fmaxf(x, 0.f) + log1pf(expf(-fabsf(x)));
    return x * tanhf(sp);
}

// ---------------- kernel 0: pad dw0 + pw0 weights ----------------
__global__ void pad_w_kernel(const float* __restrict__ dw0, const float* __restrict__ pw0)
{
    int idx = blockIdx.x * blockDim.x + threadIdx.x;
    if (idx < 9 * P0) {
        int c = idx % P0;
        int k = idx / P0;
        g_dw0pad[idx] = (c < CIN0) ? dw0[k * CIN0 + c] : 0.f;
    }
    if (idx < P0 * 128) {
        int n = idx % 128;
        int k = idx / 128;
        g_pw0pad[idx] = (k < CIN0) ? pw0[k * 128 + n] : 0.f;
    }
}

// ---------------- kernel 1: cost volume (+ concat fold in DXB==0 pass) ----------------
template<int DXB, int NDX>
__global__ __launch_bounds__(128)
void cost_kernel(const float* __restrict__ prv, const float* __restrict__ nxt,
                 float* __restrict__ x0)
{
    __shared__ float sbuf[16 * 661];
    __shared__ float sout[NDX * 9 * 257];

    const int tid  = threadIdx.x;
    const int lane = tid & 31;
    const int wp   = tid >> 5;
    const int bx = blockIdx.x, by = blockIdx.y, b = blockIdx.z;

    const int x    = bx * 32 + lane;
    const int y0   = by * 8 + wp * 2;
    const size_t pix0 = (size_t)(b * Hn + y0) * Wn + x;
    const size_t pix1 = pix0 + Wn;

    float acc0[NDX * 9], acc1[NDX * 9];
#pragma unroll
    for (int t = 0; t < NDX * 9; t++) { acc0[t] = 0.f; acc1[t] = 0.f; }

#pragma unroll 1
    for (int chp = 0; chp < 4; chp++) {
        __syncthreads();
#pragma unroll 4
        for (int k = 0; k < 80; k++) {
            int i = tid + k * 128;
            int c = i & 15;
            int rest = i >> 4;
            int xs = rest % 40;
            int r  = rest / 40;
            int gy = by * 8 + r - 4;
            int gx = bx * 32 + xs - 4;
            float v = 0.f;
            if (gy >= 0 && gy < Hn && gx >= 0 && gx < Wn)
                v = nxt[((size_t)(b * Hn + gy) * Wn + gx) * Cn + chp * 16 + c];
            sbuf[c * 661 + r * 41 + xs] = v;
        }
        __syncthreads();

#pragma unroll 1
        for (int c4 = 0; c4 < 4; c4++) {
            float4 pa = *(const float4*)(prv + pix0 * Cn + chp * 16 + c4 * 4);
            float4 pb = *(const float4*)(prv + pix1 * Cn + chp * 16 + c4 * 4);
            float pav[4] = {pa.x, pa.y, pa.z, pa.w};
            float pbv[4] = {pb.x, pb.y, pb.z, pb.w};
#pragma unroll
            for (int cc = 0; cc < 4; cc++) {
                const float* splane = &sbuf[(c4 * 4 + cc) * 661];
#pragma unroll
                for (int rr = 0; rr < 10; rr++) {
                    const float* q = &splane[(wp * 2 + rr) * 41 + lane + DXB];
#pragma unroll
                    for (int d = 0; d < NDX; d++) {
                        float qv = q[d];
                        if (rr < 9)  acc0[rr * NDX + d]       = fmaf(pav[cc], qv, acc0[rr * NDX + d]);
                        if (rr >= 1) acc1[(rr - 1) * NDX + d] = fmaf(pbv[cc], qv, acc1[(rr - 1) * NDX + d]);
                    }
                }
            }
        }
    }

    __syncthreads();
    const int pl0 = wp * 64 + lane;
#pragma unroll
    for (int t = 0; t < NDX * 9; t++) {
        float v0 = acc0[t] * (1.f / 64.f); v0 = (v0 > 0.f) ? v0 : 0.1f * v0;
        float v1 = acc1[t] * (1.f / 64.f); v1 = (v1 > 0.f) ? v1 : 0.1f * v1;
        sout[t * 257 + pl0]      = v0;
        sout[t * 257 + pl0 + 32] = v1;
    }
    __syncthreads();

    const int TOT = 256 * NDX * 9;
    for (int i = tid; i < TOT; i += 128) {
        int px = i / (NDX * 9);
        int t  = i % (NDX * 9);
        int dy = t / NDX, d = t % NDX;
        int yl = px >> 5, xx = px & 31;
        size_t pix = (size_t)(b * Hn + by * 8 + yl) * Wn + bx * 32 + xx;
        x0[pix * P0 + dy * 9 + DXB + d] = sout[t * 257 + px];
    }

    if (DXB == 0) {
        // concat prv/nxt + zero pad, coalesced (64-float runs)
        for (int j = tid; j < 256 * 64; j += 128) {
            int px = j >> 6, c = j & 63;
            int yl = px >> 5, xx = px & 31;
            size_t pix = (size_t)(b * Hn + by * 8 + yl) * Wn + bx * 32 + xx;
            x0[pix * P0 + CV + c]      = prv[pix * Cn + c];
            x0[pix * P0 + CV + 64 + c] = nxt[pix * Cn + c];
            if (c >= 57) x0[pix * P0 + 152 + c] = 0.f;   // 209..215
        }
    }
}

// ---------------- kernel 3: fused depthwise-3x3 + SGEMM + bias + mish ----------------
// X:[NPIX, ldX] activations; dwW:[9, ldX]; Wp:[KTILES*8, BN_]; Y:[NPIX, BN_]
// BM=128, BK=8, 256 threads, microtile 8 x TN_.
template<int BN_, int TN_, int KTILES>
__global__ __launch_bounds__(256)
void sgemm_dw_mish(const float* __restrict__ X, int ldX,
                   const float* __restrict__ dwW,
                   const float* __restrict__ Wp,
                   const float* __restrict__ bias,
                   float* __restrict__ Y)
{
    __shared__ float As[2][8][128];
    __shared__ float Bs[2][8][BN_];

    const int tid = threadIdx.x;
    const int px0 = blockIdx.x * 128;

    // A loader thread: row = tid/2, channel quad = (tid&1)*4
    const int arow = tid >> 1;
    const int acol = (tid & 1) * 4;
    const int pix  = px0 + arow;
    const int wpx  = pix % Wn;
    const int hpx  = (pix / Wn) % Hn;
    const float* xbase = X + (size_t)pix * ldX + acol;
    const float* wbase = dwW + acol;

    int  toff[9];
    bool tval[9];
#pragma unroll
    for (int dy = 0; dy < 3; dy++)
#pragma unroll
        for (int dx = 0; dx < 3; dx++) {
            int t = dy * 3 + dx;
            tval[t] = (hpx + dy - 1 >= 0) && (hpx + dy - 1 < Hn) &&
                      (wpx + dx - 1 >= 0) && (wpx + dx - 1 < Wn);
            toff[t] = ((dy - 1) * Wn + (dx - 1)) * ldX;
        }

    constexpr int BLOADERS = BN_ * 2;
    const int brow = tid / (BN_ / 4);
    const int bcol = (tid % (BN_ / 4)) * 4;
    const float* bptr = Wp + (size_t)brow * BN_ + bcol;

    const int tcx = tid & 15;
    const int tcy = tid >> 4;

    float acc[8][TN_];
#pragma unroll
    for (int m = 0; m < 8; m++)
#pragma unroll
        for (int n = 0; n < TN_; n++) acc[m][n] = 0.f;

    // dw-fused A-tile compute for k-tile kt
    auto dw_tile = [&](int kt) -> float4 {
        const int ch = kt * 8;
        float4 a = make_float4(0.f, 0.f, 0.f, 0.f);
#pragma unroll
        for (int t = 0; t < 9; t++) {
            if (tval[t]) {
                float4 xv = *(const float4*)(xbase + toff[t] + ch);
                float4 wv = *(const float4*)(wbase + t * ldX + ch);
                a.x = fmaf(xv.x, wv.x, a.x);
                a.y = fmaf(xv.y, wv.y, a.y);
                a.z = fmaf(xv.z, wv.z, a.z);
                a.w = fmaf(xv.w, wv.w, a.w);
            }
        }
        return a;
    };

    float4 av = dw_tile(0);
    float4 bv;
    if (tid < BLOADERS) bv = *(const float4*)bptr;

    As[0][acol + 0][arow] = av.x;
    As[0][acol + 1][arow] = av.y;
    As[0][acol + 2][arow] = av.z;
    As[0][acol + 3][arow] = av.w;
    if (tid < BLOADERS) *(float4*)&Bs[0][brow][bcol] = bv;
    __syncthreads();

#pragma unroll 1
    for (int kt = 0; kt < KTILES; kt++) {
        const int buf = kt & 1;
        if (kt + 1 < KTILES) {
            av = dw_tile(kt + 1);
            if (tid < BLOADERS) bv = *(const float4*)(bptr + (size_t)(kt + 1) * 8 * BN_);
        }
#pragma unroll
        for (int kk = 0; kk < 8; kk++) {
            float4 a0 = *(const float4*)&As[buf][kk][tcy * 4];
            float4 a1 = *(const float4*)&As[buf][kk][tcy * 4 + 64];
            float ar[8] = {a0.x, a0.y, a0.z, a0.w, a1.x, a1.y, a1.z, a1.w};
            float br[TN_];
            if constexpr (TN_ == 8) {
                float4 b0 = *(const float4*)&Bs[buf][kk][tcx * 4];
                float4 b1 = *(const float4*)&Bs[buf][kk][tcx * 4 + 64];
                br[0] = b0.x; br[1] = b0.y; br[2] = b0.z; br[3] = b0.w;
                br[4] = b1.x; br[5] = b1.y; br[6] = b1.z; br[7] = b1.w;
            } else if constexpr (TN_ == 4) {
                float4 b0 = *(const float4*)&Bs[buf][kk][tcx * 4];
                br[0] = b0.x; br[1] = b0.y; br[2] = b0.z; br[3] = b0.w;
            } else if constexpr (TN_ == 2) {
                float2 b0 = *(const float2*)&Bs[buf][kk][tcx * 2];
                br[0] = b0.x; br[1] = b0.y;
            } else {
                br[0] = Bs[buf][kk][tcx];
            }
#pragma unroll
            for (int m = 0; m < 8; m++)
#pragma unroll
                for (int n = 0; n < TN_; n++)
                    acc[m][n] = fmaf(ar[m], br[n], acc[m][n]);
        }
        if (kt + 1 < KTILES) {
            const int nb = buf ^ 1;
            As[nb][acol + 0][arow] = av.x;
            As[nb][acol + 1][arow] = av.y;
            As[nb][acol + 2][arow] = av.z;
            As[nb][acol + 3][arow] = av.w;
            if (tid < BLOADERS) *(float4*)&Bs[nb][brow][bcol] = bv;
        }
        __syncthreads();
    }

    float bb[TN_];
    if constexpr (TN_ == 8) {
        float4 t0 = *(const float4*)&bias[tcx * 4];
        float4 t1 = *(const float4*)&bias[tcx * 4 + 64];
        bb[0]=t0.x; bb[1]=t0.y; bb[2]=t0.z; bb[3]=t0.w;
        bb[4]=t1.x; bb[5]=t1.y; bb[6]=t1.z; bb[7]=t1.w;
    } else if constexpr (TN_ == 4) {
        float4 t0 = *(const float4*)&bias[tcx * 4];
        bb[0]=t0.x; bb[1]=t0.y; bb[2]=t0.z; bb[3]=t0.w;
    } else if constexpr (TN_ == 2) {
        float2 t0 = *(const float2*)&bias[tcx * 2];
        bb[0]=t0.x; bb[1]=t0.y;
    } else {
        bb[0] = bias[tcx];
    }

#pragma unroll
    for (int g = 0; g < 2; g++) {
#pragma unroll
        for (int m = 0; m < 4; m++) {
            int px = px0 + tcy * 4 + m + g * 64;
            float* yr = Y + (size_t)px * BN_;
            float ov[TN_];
#pragma unroll
            for (int n = 0; n < TN_; n++) ov[n] = mish(acc[g * 4 + m][n] + bb[n]);
            if constexpr (TN_ == 8) {
                *(float4*)&yr[tcx * 4]      = make_float4(ov[0], ov[1], ov[2], ov[3]);
                *(float4*)&yr[tcx * 4 + 64] = make_float4(ov[4], ov[5], ov[6], ov[7]);
            } else if constexpr (TN_ == 4) {
                *(float4*)&yr[tcx * 4] = make_float4(ov[0], ov[1], ov[2], ov[3]);
            } else if constexpr (TN_ == 2) {
                *(float2*)&yr[tcx * 2] = make_float2(ov[0], ov[1]);
            } else {
                yr[tcx] = ov[0];
            }
        }
    }
}

// ---------------- kernel 4: BN + 3x3 flow conv + scale ----------------
__global__ void final_kernel(const float* __restrict__ X,
                             const float* __restrict__ gamma, const float* __restrict__ beta,
                             const float* __restrict__ mean,  const float* __restrict__ var,
                             const float* __restrict__ Wf, float* __restrict__ out)
{
    int pix = blockIdx.x * blockDim.x + threadIdx.x;
    if (pix >= NPIX) return;
    int w = pix % Wn;
    int h = (pix / Wn) % Hn;
    int b = pix / (Wn * Hn);

    float sc[16], sh[16];
#pragma unroll
    for (int c = 0; c < 16; c++) {
        float s = gamma[c] * rsqrtf(var[c] + BN_EPS);
        sc[c] = s;
        sh[c] = beta[c] - mean[c] * s;
    }

    float f0 = 0.f, f1 = 0.f;
#pragma unroll
    for (int ky = 0; ky < 3; ky++) {
        int hh = h + ky - 1;
        if (hh < 0 || hh >= Hn) continue;
#pragma unroll
        for (int kx = 0; kx < 3; kx++) {
            int ww = w + kx - 1;
            if (ww < 0 || ww >= Wn) continue;
            const float* xr = X + ((size_t)((b * Hn + hh) * Wn + ww)) * 16;
            const float* wr = Wf + (ky * 3 + kx) * 16 * 2;
#pragma unroll
            for (int c = 0; c < 16; c++) {
                float xv = xr[c] * sc[c] + sh[c];
                f0 += xv * wr[c * 2 + 0];
                f1 += xv * wr[c * 2 + 1];
            }
        }
    }
    out[(size_t)pix * 2 + 0] = FLOW_SCALE * f0;
    out[(size_t)pix * 2 + 1] = FLOW_SCALE * f1;
}

// ---------------- launch ----------------
extern "C" void kernel_launch(void* const* d_in, const int* in_sizes, int n_in,
                              void* d_out, int out_size)
{
    const float* prv   = (const float*)d_in[0];
    const float* nxt   = (const float*)d_in[1];
    const float* dw0   = (const float*)d_in[2];
    const float* pw0   = (const float*)d_in[3];
    const float* b0    = (const float*)d_in[4];
    const float* dw1   = (const float*)d_in[5];
    const float* pw1   = (const float*)d_in[6];
    const float* b1    = (const float*)d_in[7];
    const float* dw2   = (const float*)d_in[8];
    const float* pw2   = (const float*)d_in[9];
    const float* b2    = (const float*)d_in[10];
    const float* dw3   = (const float*)d_in[11];
    const float* pw3   = (const float*)d_in[12];
    const float* b3    = (const float*)d_in[13];
    const float* bng   = (const float*)d_in[14];
    const float* bnb   = (const float*)d_in[15];
    const float* bnm   = (const float*)d_in[16];
    const float* bnv   = (const float*)d_in[17];
    const float* flw   = (const float*)d_in[18];
    float* out = (float*)d_out;

    float *A = nullptr, *Bb = nullptr, *W0 = nullptr, *PW0 = nullptr;
    cudaGetSymbolAddress((void**)&A,   g_bufA);
    cudaGetSymbolAddress((void**)&Bb,  g_bufB);
    cudaGetSymbolAddress((void**)&W0,  g_dw0pad);
    cudaGetSymbolAddress((void**)&PW0, g_pw0pad);

    pad_w_kernel<<<(P0 * 128 + 255) / 256, 256>>>(dw0, pw0);

    // cost volume + concat -> A [NPIX, 216]
    {
        dim3 grid(Wn / 32, Hn / 8, Bn);
        cost_kernel<0, 5><<<grid, 128>>>(prv, nxt, A);
        cost_kernel<5, 4><<<grid, 128>>>(prv, nxt, A);
    }

    // layer 0: fused dw+pw(A,216 -> Bb,128)
    sgemm_dw_mish<128, 8, P0 / 8><<<NPIX / 128, 256>>>(A, P0, W0, PW0, b0, Bb);
    // layer 1: fused dw+pw(Bb,128 -> A,64)
    sgemm_dw_mish<64, 4, 128 / 8><<<NPIX / 128, 256>>>(Bb, 128, dw1, pw1, b1, A);
    // layer 2: fused dw+pw(A,64 -> Bb,32)
    sgemm_dw_mish<32, 2, 64 / 8><<<NPIX / 128, 256>>>(A, 64, dw2, pw2, b2, Bb);
    // layer 3: fused dw+pw(Bb,32 -> A,16)
    sgemm_dw_mish<16, 1, 32 / 8><<<NPIX / 128, 256>>>(Bb, 32, dw3, pw3, b3, A);

    final_kernel<<<(NPIX + 127) / 128, 128>>>(A, bng, bnb, bnm, bnv, flw, out);
}

// round 6
// speedup vs baseline: 1.4995x; 1.4995x over previous
#include <cuda_runtime.h>
#include <cuda_bf16.h>
#include <math.h>

// ---------------- problem constants ----------------
#define Bn 8
#define Hn 192
#define Wn 192
#define Cn 64
#define NPIX (Bn*Hn*Wn)          // 294912
#define CV 81
#define CIN0 209
#define P0 216                    // padded channel stride (27 * 8)
#define FLOW_SCALE 271.52900393598527f
#define BN_EPS 1e-3f

// ---------------- scratch ----------------
__device__ float g_bufA[(size_t)NPIX * P0];
__device__ float g_bufB[(size_t)NPIX * P0];
__device__ float g_dw0pad[9 * P0];
__device__ float g_pw0pad[P0 * 128];

__device__ __forceinline__ float mish(float x) {
    float sp = fmaxf(x, 0.f) + log1pf(expf(-fabsf(x)));
    return x * tanhf(sp);
}

// ---------------- packed f32x2 helpers ----------------
__device__ __forceinline__ unsigned long long pack2(float x, float y) {
    unsigned long long r;
    asm("mov.b64 %0, {%1, %2};" : "=l"(r) : "f"(x), "f"(y));
    return r;
}
__device__ __forceinline__ void unpack2(unsigned long long v, float& x, float& y) {
    asm("mov.b64 {%0, %1}, %2;" : "=f"(x), "=f"(y) : "l"(v));
}
__device__ __forceinline__ void ffma2(unsigned long long& c, unsigned long long a, unsigned long long b) {
    asm("fma.rn.f32x2 %0, %1, %2, %0;" : "+l"(c) : "l"(a), "l"(b));
}

// ---------------- kernel 0: pad dw0 + pw0 weights ----------------
__global__ void pad_w_kernel(const float* __restrict__ dw0, const float* __restrict__ pw0)
{
    int idx = blockIdx.x * blockDim.x + threadIdx.x;
    if (idx < 9 * P0) {
        int c = idx % P0;
        int k = idx / P0;
        g_dw0pad[idx] = (c < CIN0) ? dw0[k * CIN0 + c] : 0.f;
    }
    if (idx < P0 * 128) {
        int n = idx % 128;
        int k = idx / 128;
        g_pw0pad[idx] = (k < CIN0) ? pw0[k * 128 + n] : 0.f;
    }
}

// ---------------- kernel 1: cost volume (+ concat fold in DXB==0 pass) ----------------
template<int DXB, int NDX>
__global__ __launch_bounds__(128)
void cost_kernel(const float* __restrict__ prv, const float* __restrict__ nxt,
                 float* __restrict__ x0)
{
    __shared__ float sbuf[16 * 661];
    __shared__ float sout[NDX * 9 * 257];

    const int tid  = threadIdx.x;
    const int lane = tid & 31;
    const int wp   = tid >> 5;
    const int bx = blockIdx.x, by = blockIdx.y, b = blockIdx.z;

    const int x    = bx * 32 + lane;
    const int y0   = by * 8 + wp * 2;
    const size_t pix0 = (size_t)(b * Hn + y0) * Wn + x;
    const size_t pix1 = pix0 + Wn;

    float acc0[NDX * 9], acc1[NDX * 9];
#pragma unroll
    for (int t = 0; t < NDX * 9; t++) { acc0[t] = 0.f; acc1[t] = 0.f; }

#pragma unroll 1
    for (int chp = 0; chp < 4; chp++) {
        __syncthreads();
#pragma unroll 4
        for (int k = 0; k < 80; k++) {
            int i = tid + k * 128;
            int c = i & 15;
            int rest = i >> 4;
            int xs = rest % 40;
            int r  = rest / 40;
            int gy = by * 8 + r - 4;
            int gx = bx * 32 + xs - 4;
            float v = 0.f;
            if (gy >= 0 && gy < Hn && gx >= 0 && gx < Wn)
                v = nxt[((size_t)(b * Hn + gy) * Wn + gx) * Cn + chp * 16 + c];
            sbuf[c * 661 + r * 41 + xs] = v;
        }
        __syncthreads();

#pragma unroll 1
        for (int c4 = 0; c4 < 4; c4++) {
            float4 pa = *(const float4*)(prv + pix0 * Cn + chp * 16 + c4 * 4);
            float4 pb = *(const float4*)(prv + pix1 * Cn + chp * 16 + c4 * 4);
            float pav[4] = {pa.x, pa.y, pa.z, pa.w};
            float pbv[4] = {pb.x, pb.y, pb.z, pb.w};
#pragma unroll
            for (int cc = 0; cc < 4; cc++) {
                const float* splane = &sbuf[(c4 * 4 + cc) * 661];
#pragma unroll
                for (int rr = 0; rr < 10; rr++) {
                    const float* q = &splane[(wp * 2 + rr) * 41 + lane + DXB];
#pragma unroll
                    for (int d = 0; d < NDX; d++) {
                        float qv = q[d];
                        if (rr < 9)  acc0[rr * NDX + d]       = fmaf(pav[cc], qv, acc0[rr * NDX + d]);
                        if (rr >= 1) acc1[(rr - 1) * NDX + d] = fmaf(pbv[cc], qv, acc1[(rr - 1) * NDX + d]);
                    }
                }
            }
        }
    }

    __syncthreads();
    const int pl0 = wp * 64 + lane;
#pragma unroll
    for (int t = 0; t < NDX * 9; t++) {
        float v0 = acc0[t] * (1.f / 64.f); v0 = (v0 > 0.f) ? v0 : 0.1f * v0;
        float v1 = acc1[t] * (1.f / 64.f); v1 = (v1 > 0.f) ? v1 : 0.1f * v1;
        sout[t * 257 + pl0]      = v0;
        sout[t * 257 + pl0 + 32] = v1;
    }
    __syncthreads();

    const int TOT = 256 * NDX * 9;
    for (int i = tid; i < TOT; i += 128) {
        int px = i / (NDX * 9);
        int t  = i % (NDX * 9);
        int dy = t / NDX, d = t % NDX;
        int yl = px >> 5, xx = px & 31;
        size_t pix = (size_t)(b * Hn + by * 8 + yl) * Wn + bx * 32 + xx;
        x0[pix * P0 + dy * 9 + DXB + d] = sout[t * 257 + px];
    }

    if (DXB == 0) {
        for (int j = tid; j < 256 * 64; j += 128) {
            int px = j >> 6, c = j & 63;
            int yl = px >> 5, xx = px & 31;
            size_t pix = (size_t)(b * Hn + by * 8 + yl) * Wn + bx * 32 + xx;
            x0[pix * P0 + CV + c]      = prv[pix * Cn + c];
            x0[pix * P0 + CV + 64 + c] = nxt[pix * Cn + c];
            if (c >= 57) x0[pix * P0 + 152 + c] = 0.f;   // 209..215
        }
    }
}

// ---------------- kernel 2: depthwise 3x3 SAME, float4 channels ----------------
__global__ void dw4_kernel(const float* __restrict__ X, const float* __restrict__ Wd,
                           float* __restrict__ Y, int quads, int stride)
{
    int idx = blockIdx.x * blockDim.x + threadIdx.x;
    int total = NPIX * quads;
    if (idx >= total) return;
    int q = idx % quads;
    int pix = idx / quads;
    int w = pix % Wn;
    int h = (pix / Wn) % Hn;
    int b = pix / (Wn * Hn);

    float4 acc = make_float4(0.f, 0.f, 0.f, 0.f);
#pragma unroll
    for (int ky = 0; ky < 3; ky++) {
        int hh = h + ky - 1;
        if (hh < 0 || hh >= Hn) continue;
#pragma unroll
        for (int kx = 0; kx < 3; kx++) {
            int ww = w + kx - 1;
            if (ww < 0 || ww >= Wn) continue;
            float4 xv = *(const float4*)(X + ((size_t)((b * Hn + hh) * Wn + ww)) * stride + q * 4);
            float4 wv = *(const float4*)(Wd + (ky * 3 + kx) * stride + q * 4);
            acc.x = fmaf(xv.x, wv.x, acc.x);
            acc.y = fmaf(xv.y, wv.y, acc.y);
            acc.z = fmaf(xv.z, wv.z, acc.z);
            acc.w = fmaf(xv.w, wv.w, acc.w);
        }
    }
    *(float4*)(Y + (size_t)pix * stride + q * 4) = acc;
}

// ---------------- kernel 3: SGEMM (f32x2) + bias + mish ----------------
// BM=128, BK=8, 256 threads, microtile 8 x TN_ via 4 m-pairs of f32x2.
template<int BN_, int TN_, int KTILES>
__global__ __launch_bounds__(256)
void sgemm_mish(const float* __restrict__ X, int ldX,
                const float* __restrict__ Wp,
                const float* __restrict__ bias,
                float* __restrict__ Y)
{
    __shared__ float As[2][8][128];
    __shared__ float Bs[2][8][BN_];

    const int tid = threadIdx.x;
    const int px0 = blockIdx.x * 128;

    const int arow = tid >> 1;
    const int acol = (tid & 1) * 4;
    const float* aptr = X + (size_t)(px0 + arow) * ldX + acol;

    constexpr int BLOADERS = BN_ * 2;
    const int brow = tid / (BN_ / 4);
    const int bcol = (tid % (BN_ / 4)) * 4;
    const float* bptr = Wp + (size_t)brow * BN_ + bcol;

    const int tcx = tid & 15;
    const int tcy = tid >> 4;

    // acc pairs: accp[j][n] = (acc[2j][n], acc[2j+1][n]), m-pairs from LDS.128 halves
    unsigned long long accp[4][TN_];
#pragma unroll
    for (int j = 0; j < 4; j++)
#pragma unroll
        for (int n = 0; n < TN_; n++) accp[j][n] = 0ULL;

    float4 av = *(const float4*)aptr;
    float4 bv;
    if (tid < BLOADERS) bv = *(const float4*)bptr;

    As[0][acol + 0][arow] = av.x;
    As[0][acol + 1][arow] = av.y;
    As[0][acol + 2][arow] = av.z;
    As[0][acol + 3][arow] = av.w;
    if (tid < BLOADERS) *(float4*)&Bs[0][brow][bcol] = bv;
    __syncthreads();

#pragma unroll 1
    for (int kt = 0; kt < KTILES; kt++) {
        const int buf = kt & 1;
        if (kt + 1 < KTILES) {
            av = *(const float4*)(aptr + (kt + 1) * 8);
            if (tid < BLOADERS) bv = *(const float4*)(bptr + (size_t)(kt + 1) * 8 * BN_);
        }
#pragma unroll
        for (int kk = 0; kk < 8; kk++) {
            float4 a0 = *(const float4*)&As[buf][kk][tcy * 4];
            float4 a1 = *(const float4*)&As[buf][kk][tcy * 4 + 64];
            unsigned long long ap[4];
            ap[0] = pack2(a0.x, a0.y);
            ap[1] = pack2(a0.z, a0.w);
            ap[2] = pack2(a1.x, a1.y);
            ap[3] = pack2(a1.z, a1.w);

            float br[TN_];
            if constexpr (TN_ == 8) {
                float4 b0 = *(const float4*)&Bs[buf][kk][tcx * 4];
                float4 b1 = *(const float4*)&Bs[buf][kk][tcx * 4 + 64];
                br[0] = b0.x; br[1] = b0.y; br[2] = b0.z; br[3] = b0.w;
                br[4] = b1.x; br[5] = b1.y; br[6] = b1.z; br[7] = b1.w;
            } else if constexpr (TN_ == 4) {
                float4 b0 = *(const float4*)&Bs[buf][kk][tcx * 4];
                br[0] = b0.x; br[1] = b0.y; br[2] = b0.z; br[3] = b0.w;
            } else if constexpr (TN_ == 2) {
                float2 b0 = *(const float2*)&Bs[buf][kk][tcx * 2];
                br[0] = b0.x; br[1] = b0.y;
            } else {
                br[0] = Bs[buf][kk][tcx];
            }
            unsigned long long bd[TN_];
#pragma unroll
            for (int n = 0; n < TN_; n++) bd[n] = pack2(br[n], br[n]);
#pragma unroll
            for (int j = 0; j < 4; j++)
#pragma unroll
                for (int n = 0; n < TN_; n++)
                    ffma2(accp[j][n], ap[j], bd[n]);
        }
        if (kt + 1 < KTILES) {
            const int nb = buf ^ 1;
            As[nb][acol + 0][arow] = av.x;
            As[nb][acol + 1][arow] = av.y;
            As[nb][acol + 2][arow] = av.z;
            As[nb][acol + 3][arow] = av.w;
            if (tid < BLOADERS) *(float4*)&Bs[nb][brow][bcol] = bv;
        }
        __syncthreads();
    }

    // unpack accumulators
    float acc[8][TN_];
#pragma unroll
    for (int j = 0; j < 4; j++)
#pragma unroll
        for (int n = 0; n < TN_; n++)
            unpack2(accp[j][n], acc[2 * j][n], acc[2 * j + 1][n]);

    float bb[TN_];
    if constexpr (TN_ == 8) {
        float4 t0 = *(const float4*)&bias[tcx * 4];
        float4 t1 = *(const float4*)&bias[tcx * 4 + 64];
        bb[0]=t0.x; bb[1]=t0.y; bb[2]=t0.z; bb[3]=t0.w;
        bb[4]=t1.x; bb[5]=t1.y; bb[6]=t1.z; bb[7]=t1.w;
    } else if constexpr (TN_ == 4) {
        float4 t0 = *(const float4*)&bias[tcx * 4];
        bb[0]=t0.x; bb[1]=t0.y; bb[2]=t0.z; bb[3]=t0.w;
    } else if constexpr (TN_ == 2) {
        float2 t0 = *(const float2*)&bias[tcx * 2];
        bb[0]=t0.x; bb[1]=t0.y;
    } else {
        bb[0] = bias[tcx];
    }

#pragma unroll
    for (int g = 0; g < 2; g++) {
#pragma unroll
        for (int m = 0; m < 4; m++) {
            int px = px0 + tcy * 4 + m + g * 64;
            float* yr = Y + (size_t)px * BN_;
            float ov[TN_];
#pragma unroll
            for (int n = 0; n < TN_; n++) ov[n] = mish(acc[g * 4 + m][n] + bb[n]);
            if constexpr (TN_ == 8) {
                *(float4*)&yr[tcx * 4]      = make_float4(ov[0], ov[1], ov[2], ov[3]);
                *(float4*)&yr[tcx * 4 + 64] = make_float4(ov[4], ov[5], ov[6], ov[7]);
            } else if constexpr (TN_ == 4) {
                *(float4*)&yr[tcx * 4] = make_float4(ov[0], ov[1], ov[2], ov[3]);
            } else if constexpr (TN_ == 2) {
                *(float2*)&yr[tcx * 2] = make_float2(ov[0], ov[1]);
            } else {
                yr[tcx] = ov[0];
            }
        }
    }
}

// ---------------- kernel 4: BN + 3x3 flow conv + scale ----------------
__global__ void final_kernel(const float* __restrict__ X,
                             const float* __restrict__ gamma, const float* __restrict__ beta,
                             const float* __restrict__ mean,  const float* __restrict__ var,
                             const float* __restrict__ Wf, float* __restrict__ out)
{
    int pix = blockIdx.x * blockDim.x + threadIdx.x;
    if (pix >= NPIX) return;
    int w = pix % Wn;
    int h = (pix / Wn) % Hn;
    int b = pix / (Wn * Hn);

    float sc[16], sh[16];
#pragma unroll
    for (int c = 0; c < 16; c++) {
        float s = gamma[c] * rsqrtf(var[c] + BN_EPS);
        sc[c] = s;
        sh[c] = beta[c] - mean[c] * s;
    }

    float f0 = 0.f, f1 = 0.f;
#pragma unroll
    for (int ky = 0; ky < 3; ky++) {
        int hh = h + ky - 1;
        if (hh < 0 || hh >= Hn) continue;
#pragma unroll
        for (int kx = 0; kx < 3; kx++) {
            int ww = w + kx - 1;
            if (ww < 0 || ww >= Wn) continue;
            const float* xr = X + ((size_t)((b * Hn + hh) * Wn + ww)) * 16;
            const float* wr = Wf + (ky * 3 + kx) * 16 * 2;
#pragma unroll
            for (int c = 0; c < 16; c++) {
                float xv = xr[c] * sc[c] + sh[c];
                f0 += xv * wr[c * 2 + 0];
                f1 += xv * wr[c * 2 + 1];
            }
        }
    }
    out[(size_t)pix * 2 + 0] = FLOW_SCALE * f0;
    out[(size_t)pix * 2 + 1] = FLOW_SCALE * f1;
}

// ---------------- launch ----------------
extern "C" void kernel_launch(void* const* d_in, const int* in_sizes, int n_in,
                              void* d_out, int out_size)
{
    const float* prv   = (const float*)d_in[0];
    const float* nxt   = (const float*)d_in[1];
    const float* dw0   = (const float*)d_in[2];
    const float* pw0   = (const float*)d_in[3];
    const float* b0    = (const float*)d_in[4];
    const float* dw1   = (const float*)d_in[5];
    const float* pw1   = (const float*)d_in[6];
    const float* b1    = (const float*)d_in[7];
    const float* dw2   = (const float*)d_in[8];
    const float* pw2   = (const float*)d_in[9];
    const float* b2    = (const float*)d_in[10];
    const float* dw3   = (const float*)d_in[11];
    const float* pw3   = (const float*)d_in[12];
    const float* b3    = (const float*)d_in[13];
    const float* bng   = (const float*)d_in[14];
    const float* bnb   = (const float*)d_in[15];
    const float* bnm   = (const float*)d_in[16];
    const float* bnv   = (const float*)d_in[17];
    const float* flw   = (const float*)d_in[18];
    float* out = (float*)d_out;

    float *A = nullptr, *Bb = nullptr, *W0 = nullptr, *PW0 = nullptr;
    cudaGetSymbolAddress((void**)&A,   g_bufA);
    cudaGetSymbolAddress((void**)&Bb,  g_bufB);
    cudaGetSymbolAddress((void**)&W0,  g_dw0pad);
    cudaGetSymbolAddress((void**)&PW0, g_pw0pad);

    pad_w_kernel<<<(P0 * 128 + 255) / 256, 256>>>(dw0, pw0);

    // cost volume + concat -> A [NPIX, 216]
    {
        dim3 grid(Wn / 32, Hn / 8, Bn);
        cost_kernel<0, 5><<<grid, 128>>>(prv, nxt, A);
        cost_kernel<5, 4><<<grid, 128>>>(prv, nxt, A);
    }

    // layer 0
    {
        int total = NPIX * (P0 / 4);
        dw4_kernel<<<(total + 255) / 256, 256>>>(A, W0, Bb, P0 / 4, P0);
        sgemm_mish<128, 8, P0 / 8><<<NPIX / 128, 256>>>(Bb, P0, PW0, b0, A);
    }
    // layer 1
    {
        int total = NPIX * (128 / 4);
        dw4_kernel<<<(total + 255) / 256, 256>>>(A, dw1, Bb, 128 / 4, 128);
        sgemm_mish<64, 4, 128 / 8><<<NPIX / 128, 256>>>(Bb, 128, pw1, b1, A);
    }
    // layer 2
    {
        int total = NPIX * (64 / 4);
        dw4_kernel<<<(total + 255) / 256, 256>>>(A, dw2, Bb, 64 / 4, 64);
        sgemm_mish<32, 2, 64 / 8><<<NPIX / 128, 256>>>(Bb, 64, pw2, b2, A);
    }
    // layer 3
    {
        int total = NPIX * (32 / 4);
        dw4_kernel<<<(total + 255) / 256, 256>>>(A, dw3, Bb, 32 / 4, 32);
        sgemm_mish<16, 1, 32 / 8><<<NPIX / 128, 256>>>(Bb, 32, pw3, b3, A);
    }
    final_kernel<<<(NPIX + 127) / 128, 128>>>(A, bng, bnb, bnm, bnv, flw, out);
}

// round 8
// speedup vs baseline: 1.5319x; 1.0216x over previous
#include <cuda_runtime.h>
#include <cuda_bf16.h>
#include <math.h>

// ---------------- problem constants ----------------
#define Bn 8
#define Hn 192
#define Wn 192
#define Cn 64
#define NPIX (Bn*Hn*Wn)          // 294912
#define CV 81
#define CIN0 209
#define P0 216                    // padded channel stride (27 * 8)
#define FLOW_SCALE 271.52900393598527f
#define BN_EPS 1e-3f

// ---------------- scratch ----------------
__device__ float g_bufA[(size_t)NPIX * P0];
__device__ float g_bufB[(size_t)NPIX * P0];
__device__ float g_dw0pad[9 * P0];
__device__ float g_pw0pad[P0 * 128];

__device__ __forceinline__ float mish(float x) {
    float sp = fmaxf(x, 0.f) + log1pf(expf(-fabsf(x)));
    return x * tanhf(sp);
}

// ---------------- packed f32x2 helpers ----------------
__device__ __forceinline__ unsigned long long pack2(float x, float y) {
    unsigned long long r;
    asm("mov.b64 %0, {%1, %2};" : "=l"(r) : "f"(x), "f"(y));
    return r;
}
__device__ __forceinline__ void unpack2(unsigned long long v, float& x, float& y) {
    asm("mov.b64 {%0, %1}, %2;" : "=f"(x), "=f"(y) : "l"(v));
}
__device__ __forceinline__ void ffma2(unsigned long long& c, unsigned long long a, unsigned long long b) {
    asm("fma.rn.f32x2 %0, %1, %2, %0;" : "+l"(c) : "l"(a), "l"(b));
}

// ---------------- kernel 0: pad dw0 + pw0 weights ----------------
__global__ void pad_w_kernel(const float* __restrict__ dw0, const float* __restrict__ pw0)
{
    int idx = blockIdx.x * blockDim.x + threadIdx.x;
    if (idx < 9 * P0) {
        int c = idx % P0;
        int k = idx / P0;
        g_dw0pad[idx] = (c < CIN0) ? dw0[k * CIN0 + c] : 0.f;
    }
    if (idx < P0 * 128) {
        int n = idx % 128;
        int k = idx / 128;
        g_pw0pad[idx] = (k < CIN0) ? pw0[k * 128 + n] : 0.f;
    }
}

// ---------------- kernel 1: cost volume (+ concat fold in DXB==0 pass) ----------------
template<int DXB, int NDX>
__global__ __launch_bounds__(128)
void cost_kernel(const float* __restrict__ prv, const float* __restrict__ nxt,
                 float* __restrict__ x0)
{
    __shared__ float sbuf[16 * 661];
    __shared__ float sout[NDX * 9 * 257];

    const int tid  = threadIdx.x;
    const int lane = tid & 31;
    const int wp   = tid >> 5;
    const int bx = blockIdx.x, by = blockIdx.y, b = blockIdx.z;

    const int x    = bx * 32 + lane;
    const int y0   = by * 8 + wp * 2;
    const size_t pix0 = (size_t)(b * Hn + y0) * Wn + x;
    const size_t pix1 = pix0 + Wn;

    float acc0[NDX * 9], acc1[NDX * 9];
#pragma unroll
    for (int t = 0; t < NDX * 9; t++) { acc0[t] = 0.f; acc1[t] = 0.f; }

#pragma unroll 1
    for (int chp = 0; chp < 4; chp++) {
        __syncthreads();
#pragma unroll 4
        for (int k = 0; k < 80; k++) {
            int i = tid + k * 128;
            int c = i & 15;
            int rest = i >> 4;
            int xs = rest % 40;
            int r  = rest / 40;
            int gy = by * 8 + r - 4;
            int gx = bx * 32 + xs - 4;
            float v = 0.f;
            if (gy >= 0 && gy < Hn && gx >= 0 && gx < Wn)
                v = nxt[((size_t)(b * Hn + gy) * Wn + gx) * Cn + chp * 16 + c];
            sbuf[c * 661 + r * 41 + xs] = v;
        }
        __syncthreads();

#pragma unroll 1
        for (int c4 = 0; c4 < 4; c4++) {
            float4 pa = *(const float4*)(prv + pix0 * Cn + chp * 16 + c4 * 4);
            float4 pb = *(const float4*)(prv + pix1 * Cn + chp * 16 + c4 * 4);
            float pav[4] = {pa.x, pa.y, pa.z, pa.w};
            float pbv[4] = {pb.x, pb.y, pb.z, pb.w};
#pragma unroll
            for (int cc = 0; cc < 4; cc++) {
                const float* splane = &sbuf[(c4 * 4 + cc) * 661];
#pragma unroll
                for (int rr = 0; rr < 10; rr++) {
                    const float* q = &splane[(wp * 2 + rr) * 41 + lane + DXB];
#pragma unroll
                    for (int d = 0; d < NDX; d++) {
                        float qv = q[d];
                        if (rr < 9)  acc0[rr * NDX + d]       = fmaf(pav[cc], qv, acc0[rr * NDX + d]);
                        if (rr >= 1) acc1[(rr - 1) * NDX + d] = fmaf(pbv[cc], qv, acc1[(rr - 1) * NDX + d]);
                    }
                }
            }
        }
    }

    __syncthreads();
    const int pl0 = wp * 64 + lane;
#pragma unroll
    for (int t = 0; t < NDX * 9; t++) {
        float v0 = acc0[t] * (1.f / 64.f); v0 = (v0 > 0.f) ? v0 : 0.1f * v0;
        float v1 = acc1[t] * (1.f / 64.f); v1 = (v1 > 0.f) ? v1 : 0.1f * v1;
        sout[t * 257 + pl0]      = v0;
        sout[t * 257 + pl0 + 32] = v1;
    }
    __syncthreads();

    const int TOT = 256 * NDX * 9;
    for (int i = tid; i < TOT; i += 128) {
        int px = i / (NDX * 9);
        int t  = i % (NDX * 9);
        int dy = t / NDX, d = t % NDX;
        int yl = px >> 5, xx = px & 31;
        size_t pix = (size_t)(b * Hn + by * 8 + yl) * Wn + bx * 32 + xx;
        x0[pix * P0 + dy * 9 + DXB + d] = sout[t * 257 + px];
    }

    if (DXB == 0) {
        for (int j = tid; j < 256 * 64; j += 128) {
            int px = j >> 6, c = j & 63;
            int yl = px >> 5, xx = px & 31;
            size_t pix = (size_t)(b * Hn + by * 8 + yl) * Wn + bx * 32 + xx;
            x0[pix * P0 + CV + c]      = prv[pix * Cn + c];
            x0[pix * P0 + CV + 64 + c] = nxt[pix * Cn + c];
            if (c >= 57) x0[pix * P0 + 152 + c] = 0.f;   // 209..215
        }
    }
}

// ---------------- kernel 2: depthwise 3x3 SAME, float4 channels (templated) ----------------
template<int QUADS, int STRIDE, int WSTRIDE>
__global__ __launch_bounds__(256)
void dw4_kernel(const float* __restrict__ X, const float* __restrict__ Wd,
                float* __restrict__ Y)
{
    int idx = blockIdx.x * blockDim.x + threadIdx.x;
    if (idx >= NPIX * QUADS) return;
    int q = idx % QUADS;          // compile-time divisor -> mul/shift
    int pix = idx / QUADS;
    int w = pix % Wn;
    int h = (pix / Wn) % Hn;
    int b = pix / (Wn * Hn);

    float4 acc = make_float4(0.f, 0.f, 0.f, 0.f);
#pragma unroll
    for (int ky = 0; ky < 3; ky++) {
        int hh = h + ky - 1;
        if (hh < 0 || hh >= Hn) continue;
#pragma unroll
        for (int kx = 0; kx < 3; kx++) {
            int ww = w + kx - 1;
            if (ww < 0 || ww >= Wn) continue;
            float4 xv = *(const float4*)(X + ((size_t)((b * Hn + hh) * Wn + ww)) * STRIDE + q * 4);
            float4 wv = *(const float4*)(Wd + (ky * 3 + kx) * WSTRIDE + q * 4);
            acc.x = fmaf(xv.x, wv.x, acc.x);
            acc.y = fmaf(xv.y, wv.y, acc.y);
            acc.z = fmaf(xv.z, wv.z, acc.z);
            acc.w = fmaf(xv.w, wv.w, acc.w);
        }
    }
    *(float4*)(Y + (size_t)pix * STRIDE + q * 4) = acc;
}

// ---------------- kernel 3: SGEMM (f32x2) + bias + mish ----------------
// BM=128, BK=8, 256 threads, microtile 8 x TN_ via 4 m-pairs of f32x2.
template<int BN_, int TN_, int KTILES>
__global__ __launch_bounds__(256)
void sgemm_mish(const float* __restrict__ X, int ldX,
                const float* __restrict__ Wp,
                const float* __restrict__ bias,
                float* __restrict__ Y)
{
    __shared__ float As[2][8][128];
    __shared__ float Bs[2][8][BN_];

    const int tid = threadIdx.x;
    const int px0 = blockIdx.x * 128;

    const int arow = tid >> 1;
    const int acol = (tid & 1) * 4;
    const float* aptr = X + (size_t)(px0 + arow) * ldX + acol;

    constexpr int BLOADERS = BN_ * 2;
    const int brow = tid / (BN_ / 4);
    const int bcol = (tid % (BN_ / 4)) * 4;
    const float* bptr = Wp + (size_t)brow * BN_ + bcol;

    const int tcx = tid & 15;
    const int tcy = tid >> 4;

    unsigned long long accp[4][TN_];
#pragma unroll
    for (int j = 0; j < 4; j++)
#pragma unroll
        for (int n = 0; n < TN_; n++) accp[j][n] = 0ULL;

    float4 av = *(const float4*)aptr;
    float4 bv;
    if (tid < BLOADERS) bv = *(const float4*)bptr;

    As[0][acol + 0][arow] = av.x;
    As[0][acol + 1][arow] = av.y;
    As[0][acol + 2][arow] = av.z;
    As[0][acol + 3][arow] = av.w;
    if (tid < BLOADERS) *(float4*)&Bs[0][brow][bcol] = bv;
    __syncthreads();

#pragma unroll 1
    for (int kt = 0; kt < KTILES; kt++) {
        const int buf = kt & 1;
        if (kt + 1 < KTILES) {
            av = *(const float4*)(aptr + (kt + 1) * 8);
            if (tid < BLOADERS) bv = *(const float4*)(bptr + (size_t)(kt + 1) * 8 * BN_);
        }
#pragma unroll
        for (int kk = 0; kk < 8; kk++) {
            float4 a0 = *(const float4*)&As[buf][kk][tcy * 4];
            float4 a1 = *(const float4*)&As[buf][kk][tcy * 4 + 64];
            unsigned long long ap[4];
            ap[0] = pack2(a0.x, a0.y);
            ap[1] = pack2(a0.z, a0.w);
            ap[2] = pack2(a1.x, a1.y);
            ap[3] = pack2(a1.z, a1.w);

            float br[TN_];
            if constexpr (TN_ == 8) {
                float4 b0 = *(const float4*)&Bs[buf][kk][tcx * 4];
                float4 b1 = *(const float4*)&Bs[buf][kk][tcx * 4 + 64];
                br[0] = b0.x; br[1] = b0.y; br[2] = b0.z; br[3] = b0.w;
                br[4] = b1.x; br[5] = b1.y; br[6] = b1.z; br[7] = b1.w;
            } else if constexpr (TN_ == 4) {
                float4 b0 = *(const float4*)&Bs[buf][kk][tcx * 4];
                br[0] = b0.x; br[1] = b0.y; br[2] = b0.z; br[3] = b0.w;
            } else if constexpr (TN_ == 2) {
                float2 b0 = *(const float2*)&Bs[buf][kk][tcx * 2];
                br[0] = b0.x; br[1] = b0.y;
            } else {
                br[0] = Bs[buf][kk][tcx];
            }
            unsigned long long bd[TN_];
#pragma unroll
            for (int n = 0; n < TN_; n++) bd[n] = pack2(br[n], br[n]);
#pragma unroll
            for (int j = 0; j < 4; j++)
#pragma unroll
                for (int n = 0; n < TN_; n++)
                    ffma2(accp[j][n], ap[j], bd[n]);
        }
        if (kt + 1 < KTILES) {
            const int nb = buf ^ 1;
            As[nb][acol + 0][arow] = av.x;
            As[nb][acol + 1][arow] = av.y;
            As[nb][acol + 2][arow] = av.z;
            As[nb][acol + 3][arow] = av.w;
            if (tid < BLOADERS) *(float4*)&Bs[nb][brow][bcol] = bv;
        }
        __syncthreads();
    }

    float acc[8][TN_];
#pragma unroll
    for (int j = 0; j < 4; j++)
#pragma unroll
        for (int n = 0; n < TN_; n++)
            unpack2(accp[j][n], acc[2 * j][n], acc[2 * j + 1][n]);

    float bb[TN_];
    if constexpr (TN_ == 8) {
        float4 t0 = *(const float4*)&bias[tcx * 4];
        float4 t1 = *(const float4*)&bias[tcx * 4 + 64];
        bb[0]=t0.x; bb[1]=t0.y; bb[2]=t0.z; bb[3]=t0.w;
        bb[4]=t1.x; bb[5]=t1.y; bb[6]=t1.z; bb[7]=t1.w;
    } else if constexpr (TN_ == 4) {
        float4 t0 = *(const float4*)&bias[tcx * 4];
        bb[0]=t0.x; bb[1]=t0.y; bb[2]=t0.z; bb[3]=t0.w;
    } else if constexpr (TN_ == 2) {
        float2 t0 = *(const float2*)&bias[tcx * 2];
        bb[0]=t0.x; bb[1]=t0.y;
    } else {
        bb[0] = bias[tcx];
    }

#pragma unroll
    for (int g = 0; g < 2; g++) {
#pragma unroll
        for (int m = 0; m < 4; m++) {
            int px = px0 + tcy * 4 + m + g * 64;
            float* yr = Y + (size_t)px * BN_;
            float ov[TN_];
#pragma unroll
            for (int n = 0; n < TN_; n++) ov[n] = mish(acc[g * 4 + m][n] + bb[n]);
            if constexpr (TN_ == 8) {
                *(float4*)&yr[tcx * 4]      = make_float4(ov[0], ov[1], ov[2], ov[3]);
                *(float4*)&yr[tcx * 4 + 64] = make_float4(ov[4], ov[5], ov[6], ov[7]);
            } else if constexpr (TN_ == 4) {
                *(float4*)&yr[tcx * 4] = make_float4(ov[0], ov[1], ov[2], ov[3]);
            } else if constexpr (TN_ == 2) {
                *(float2*)&yr[tcx * 2] = make_float2(ov[0], ov[1]);
            } else {
                yr[tcx] = ov[0];
            }
        }
    }
}

// ---------------- kernel 4: BN + 3x3 flow conv + scale ----------------
__global__ void final_kernel(const float* __restrict__ X,
                             const float* __restrict__ gamma, const float* __restrict__ beta,
                             const float* __restrict__ mean,  const float* __restrict__ var,
                             const float* __restrict__ Wf, float* __restrict__ out)
{
    int pix = blockIdx.x * blockDim.x + threadIdx.x;
    if (pix >= NPIX) return;
    int w = pix % Wn;
    int h = (pix / Wn) % Hn;
    int b = pix / (Wn * Hn);

    float sc[16], sh[16];
#pragma unroll
    for (int c = 0; c < 16; c++) {
        float s = gamma[c] * rsqrtf(var[c] + BN_EPS);
        sc[c] = s;
        sh[c] = beta[c] - mean[c] * s;
    }

    float f0 = 0.f, f1 = 0.f;
#pragma unroll
    for (int ky = 0; ky < 3; ky++) {
        int hh = h + ky - 1;
        if (hh < 0 || hh >= Hn) continue;
#pragma unroll
        for (int kx = 0; kx < 3; kx++) {
            int ww = w + kx - 1;
            if (ww < 0 || ww >= Wn) continue;
            const float* xr = X + ((size_t)((b * Hn + hh) * Wn + ww)) * 16;
            const float* wr = Wf + (ky * 3 + kx) * 16 * 2;
#pragma unroll
            for (int c = 0; c < 16; c++) {
                float xv = xr[c] * sc[c] + sh[c];
                f0 += xv * wr[c * 2 + 0];
                f1 += xv * wr[c * 2 + 1];
            }
        }
    }
    out[(size_t)pix * 2 + 0] = FLOW_SCALE * f0;
    out[(size_t)pix * 2 + 1] = FLOW_SCALE * f1;
}

// ---------------- launch ----------------
extern "C" void kernel_launch(void* const* d_in, const int* in_sizes, int n_in,
                              void* d_out, int out_size)
{
    const float* prv   = (const float*)d_in[0];
    const float* nxt   = (const float*)d_in[1];
    const float* dw0   = (const float*)d_in[2];
    const float* pw0   = (const float*)d_in[3];
    const float* b0    = (const float*)d_in[4];
    const float* dw1   = (const float*)d_in[5];
    const float* pw1   = (const float*)d_in[6];
    const float* b1    = (const float*)d_in[7];
    const float* dw2   = (const float*)d_in[8];
    const float* pw2   = (const float*)d_in[9];
    const float* b2    = (const float*)d_in[10];
    const float* dw3   = (const float*)d_in[11];
    const float* pw3   = (const float*)d_in[12];
    const float* b3    = (const float*)d_in[13];
    const float* bng   = (const float*)d_in[14];
    const float* bnb   = (const float*)d_in[15];
    const float* bnm   = (const float*)d_in[16];
    const float* bnv   = (const float*)d_in[17];
    const float* flw   = (const float*)d_in[18];
    float* out = (float*)d_out;

    float *A = nullptr, *Bb = nullptr, *W0 = nullptr, *PW0 = nullptr;
    cudaGetSymbolAddress((void**)&A,   g_bufA);
    cudaGetSymbolAddress((void**)&Bb,  g_bufB);
    cudaGetSymbolAddress((void**)&W0,  g_dw0pad);
    cudaGetSymbolAddress((void**)&PW0, g_pw0pad);

    pad_w_kernel<<<(P0 * 128 + 255) / 256, 256>>>(dw0, pw0);

    // cost volume + concat -> A [NPIX, 216]
    {
        dim3 grid(Wn / 32, Hn / 8, Bn);
        cost_kernel<0, 5><<<grid, 128>>>(prv, nxt, A);
        cost_kernel<5, 4><<<grid, 128>>>(prv, nxt, A);
    }

    // layer 0
    dw4_kernel<54, P0, P0><<<(NPIX * 54 + 255) / 256, 256>>>(A, W0, Bb);
    sgemm_mish<128, 8, P0 / 8><<<NPIX / 128, 256>>>(Bb, P0, PW0, b0, A);
    // layer 1
    dw4_kernel<32, 128, 128><<<(NPIX * 32 + 255) / 256, 256>>>(A, dw1, Bb);
    sgemm_mish<64, 4, 16><<<NPIX / 128, 256>>>(Bb, 128, pw1, b1, A);
    // layer 2
    dw4_kernel<16, 64, 64><<<(NPIX * 16 + 255) / 256, 256>>>(A, dw2, Bb);
    sgemm_mish<32, 2, 8><<<NPIX / 128, 256>>>(Bb, 64, pw2, b2, A);
    // layer 3
    dw4_kernel<8, 32, 32><<<(NPIX * 8 + 255) / 256, 256>>>(A, dw3, Bb);
    sgemm_mish<16, 1, 4><<<NPIX / 128, 256>>>(Bb, 32, pw3, b3, A);

    final_kernel<<<(NPIX + 127) / 128, 128>>>(A, bng, bnb, bnm, bnv, flw, out);
}

// round 9
// speedup vs baseline: 1.5683x; 1.0237x over previous
#include <cuda_runtime.h>
#include <cuda_bf16.h>
#include <math.h>

// ---------------- problem constants ----------------
#define Bn 8
#define Hn 192
#define Wn 192
#define Cn 64
#define NPIX (Bn*Hn*Wn)          // 294912
#define CV 81
#define CIN0 209
#define P0 216                    // padded channel stride (27 * 8)
#define FLOW_SCALE 271.52900393598527f
#define BN_EPS 1e-3f

// ---------------- scratch ----------------
__device__ float g_bufA[(size_t)NPIX * P0];
__device__ float g_bufB[(size_t)NPIX * P0];
__device__ float g_dw0pad[9 * P0];
__device__ float g_pw0pad[P0 * 128];

__device__ __forceinline__ float mish(float x) {
    float sp = fmaxf(x, 0.f) + log1pf(expf(-fabsf(x)));
    return x * tanhf(sp);
}

// ---------------- packed f32x2 helpers ----------------
__device__ __forceinline__ unsigned long long pack2(float x, float y) {
    unsigned long long r;
    asm("mov.b64 %0, {%1, %2};" : "=l"(r) : "f"(x), "f"(y));
    return r;
}
__device__ __forceinline__ void unpack2(unsigned long long v, float& x, float& y) {
    asm("mov.b64 {%0, %1}, %2;" : "=f"(x), "=f"(y) : "l"(v));
}
__device__ __forceinline__ void ffma2(unsigned long long& c, unsigned long long a, unsigned long long b) {
    asm("fma.rn.f32x2 %0, %1, %2, %0;" : "+l"(c) : "l"(a), "l"(b));
}

// ---------------- kernel 0: pad dw0 + pw0 weights ----------------
__global__ void pad_w_kernel(const float* __restrict__ dw0, const float* __restrict__ pw0)
{
    int idx = blockIdx.x * blockDim.x + threadIdx.x;
    if (idx < 9 * P0) {
        int c = idx % P0;
        int k = idx / P0;
        g_dw0pad[idx] = (c < CIN0) ? dw0[k * CIN0 + c] : 0.f;
    }
    if (idx < P0 * 128) {
        int n = idx % 128;
        int k = idx / 128;
        g_pw0pad[idx] = (k < CIN0) ? pw0[k * 128 + n] : 0.f;
    }
}

// ---------------- kernel 1: cost volume (+ concat fold in DXB==0 pass) ----------------
template<int DXB, int NDX>
__global__ __launch_bounds__(128)
void cost_kernel(const float* __restrict__ prv, const float* __restrict__ nxt,
                 float* __restrict__ x0)
{
    __shared__ float sbuf[16 * 661];
    __shared__ float sout[NDX * 9 * 257];

    const int tid  = threadIdx.x;
    const int lane = tid & 31;
    const int wp   = tid >> 5;
    const int bx = blockIdx.x, by = blockIdx.y, b = blockIdx.z;

    const int x    = bx * 32 + lane;
    const int y0   = by * 8 + wp * 2;
    const size_t pix0 = (size_t)(b * Hn + y0) * Wn + x;
    const size_t pix1 = pix0 + Wn;

    float acc0[NDX * 9], acc1[NDX * 9];
#pragma unroll
    for (int t = 0; t < NDX * 9; t++) { acc0[t] = 0.f; acc1[t] = 0.f; }

#pragma unroll 1
    for (int chp = 0; chp < 4; chp++) {
        __syncthreads();
#pragma unroll 4
        for (int k = 0; k < 80; k++) {
            int i = tid + k * 128;
            int c = i & 15;
            int rest = i >> 4;
            int xs = rest % 40;
            int r  = rest / 40;
            int gy = by * 8 + r - 4;
            int gx = bx * 32 + xs - 4;
            float v = 0.f;
            if (gy >= 0 && gy < Hn && gx >= 0 && gx < Wn)
                v = nxt[((size_t)(b * Hn + gy) * Wn + gx) * Cn + chp * 16 + c];
            sbuf[c * 661 + r * 41 + xs] = v;
        }
        __syncthreads();

#pragma unroll 1
        for (int c4 = 0; c4 < 4; c4++) {
            float4 pa = *(const float4*)(prv + pix0 * Cn + chp * 16 + c4 * 4);
            float4 pb = *(const float4*)(prv + pix1 * Cn + chp * 16 + c4 * 4);
            float pav[4] = {pa.x, pa.y, pa.z, pa.w};
            float pbv[4] = {pb.x, pb.y, pb.z, pb.w};
#pragma unroll
            for (int cc = 0; cc < 4; cc++) {
                const float* splane = &sbuf[(c4 * 4 + cc) * 661];
#pragma unroll
                for (int rr = 0; rr < 10; rr++) {
                    const float* q = &splane[(wp * 2 + rr) * 41 + lane + DXB];
#pragma unroll
                    for (int d = 0; d < NDX; d++) {
                        float qv = q[d];
                        if (rr < 9)  acc0[rr * NDX + d]       = fmaf(pav[cc], qv, acc0[rr * NDX + d]);
                        if (rr >= 1) acc1[(rr - 1) * NDX + d] = fmaf(pbv[cc], qv, acc1[(rr - 1) * NDX + d]);
                    }
                }
            }
        }
    }

    __syncthreads();
    const int pl0 = wp * 64 + lane;
#pragma unroll
    for (int t = 0; t < NDX * 9; t++) {
        float v0 = acc0[t] * (1.f / 64.f); v0 = (v0 > 0.f) ? v0 : 0.1f * v0;
        float v1 = acc1[t] * (1.f / 64.f); v1 = (v1 > 0.f) ? v1 : 0.1f * v1;
        sout[t * 257 + pl0]      = v0;
        sout[t * 257 + pl0 + 32] = v1;
    }
    __syncthreads();

    const int TOT = 256 * NDX * 9;
    for (int i = tid; i < TOT; i += 128) {
        int px = i / (NDX * 9);
        int t  = i % (NDX * 9);
        int dy = t / NDX, d = t % NDX;
        int yl = px >> 5, xx = px & 31;
        size_t pix = (size_t)(b * Hn + by * 8 + yl) * Wn + bx * 32 + xx;
        x0[pix * P0 + dy * 9 + DXB + d] = sout[t * 257 + px];
    }

    if (DXB == 0) {
        for (int j = tid; j < 256 * 64; j += 128) {
            int px = j >> 6, c = j & 63;
            int yl = px >> 5, xx = px & 31;
            size_t pix = (size_t)(b * Hn + by * 8 + yl) * Wn + bx * 32 + xx;
            x0[pix * P0 + CV + c]      = prv[pix * Cn + c];
            x0[pix * P0 + CV + 64 + c] = nxt[pix * Cn + c];
            if (c >= 57) x0[pix * P0 + 152 + c] = 0.f;   // 209..215
        }
    }
}

// ---------------- kernel 2: depthwise 3x3 SAME, float4 channels, 4 y-outputs/thread ----------------
template<int QUADS, int STRIDE, int WSTRIDE>
__global__ __launch_bounds__(256)
void dw4y_kernel(const float* __restrict__ X, const float* __restrict__ Wd,
                 float* __restrict__ Y)
{
    int idx = blockIdx.x * blockDim.x + threadIdx.x;
    if (idx >= (NPIX / 4) * QUADS) return;
    int q    = idx % QUADS;
    int rest = idx / QUADS;
    int w    = rest % Wn;
    int rest2 = rest / Wn;
    int hg   = rest2 % (Hn / 4);
    int b    = rest2 / (Hn / 4);
    const int h0 = hg * 4;

    // 9 weight quads
    float4 wv[9];
#pragma unroll
    for (int t = 0; t < 9; t++)
        wv[t] = *(const float4*)(Wd + t * WSTRIDE + q * 4);

    float4 acc[4];
#pragma unroll
    for (int m = 0; m < 4; m++) acc[m] = make_float4(0.f, 0.f, 0.f, 0.f);

    const bool wl = (w - 1 >= 0), wr = (w + 1 < Wn);

#pragma unroll
    for (int r = 0; r < 6; r++) {            // input rows h0-1 .. h0+4
        int hh = h0 + r - 1;
        if (hh < 0 || hh >= Hn) continue;
        const float* rowp = X + ((size_t)((b * Hn + hh) * Wn + w)) * STRIDE + q * 4;
#pragma unroll
        for (int kx = 0; kx < 3; kx++) {
            if (kx == 0 && !wl) continue;
            if (kx == 2 && !wr) continue;
            float4 xv = *(const float4*)(rowp + (kx - 1) * STRIDE);
#pragma unroll
            for (int m = 0; m < 4; m++) {
                int ky = r - m;               // input row = out_y + ky - 1
                if (ky < 0 || ky > 2) continue;
                float4 wq = wv[ky * 3 + kx];
                acc[m].x = fmaf(xv.x, wq.x, acc[m].x);
                acc[m].y = fmaf(xv.y, wq.y, acc[m].y);
                acc[m].z = fmaf(xv.z, wq.z, acc[m].z);
                acc[m].w = fmaf(xv.w, wq.w, acc[m].w);
            }
        }
    }

#pragma unroll
    for (int m = 0; m < 4; m++) {
        size_t pix = (size_t)((b * Hn + h0 + m) * Wn + w);
        *(float4*)(Y + pix * STRIDE + q * 4) = acc[m];
    }
}

// ---------------- kernel 3: SGEMM (f32x2) + bias + mish ----------------
template<int BN_, int TN_, int KTILES>
__global__ __launch_bounds__(256)
void sgemm_mish(const float* __restrict__ X, int ldX,
                const float* __restrict__ Wp,
                const float* __restrict__ bias,
                float* __restrict__ Y)
{
    __shared__ float As[2][8][128];
    __shared__ float Bs[2][8][BN_];

    const int tid = threadIdx.x;
    const int px0 = blockIdx.x * 128;

    const int arow = tid >> 1;
    const int acol = (tid & 1) * 4;
    const float* aptr = X + (size_t)(px0 + arow) * ldX + acol;

    constexpr int BLOADERS = BN_ * 2;
    const int brow = tid / (BN_ / 4);
    const int bcol = (tid % (BN_ / 4)) * 4;
    const float* bptr = Wp + (size_t)brow * BN_ + bcol;

    const int tcx = tid & 15;
    const int tcy = tid >> 4;

    unsigned long long accp[4][TN_];
#pragma unroll
    for (int j = 0; j < 4; j++)
#pragma unroll
        for (int n = 0; n < TN_; n++) accp[j][n] = 0ULL;

    float4 av = *(const float4*)aptr;
    float4 bv;
    if (tid < BLOADERS) bv = *(const float4*)bptr;

    As[0][acol + 0][arow] = av.x;
    As[0][acol + 1][arow] = av.y;
    As[0][acol + 2][arow] = av.z;
    As[0][acol + 3][arow] = av.w;
    if (tid < BLOADERS) *(float4*)&Bs[0][brow][bcol] = bv;
    __syncthreads();

#pragma unroll 1
    for (int kt = 0; kt < KTILES; kt++) {
        const int buf = kt & 1;
        if (kt + 1 < KTILES) {
            av = *(const float4*)(aptr + (kt + 1) * 8);
            if (tid < BLOADERS) bv = *(const float4*)(bptr + (size_t)(kt + 1) * 8 * BN_);
        }
#pragma unroll
        for (int kk = 0; kk < 8; kk++) {
            float4 a0 = *(const float4*)&As[buf][kk][tcy * 4];
            float4 a1 = *(const float4*)&As[buf][kk][tcy * 4 + 64];
            unsigned long long ap[4];
            ap[0] = pack2(a0.x, a0.y);
            ap[1] = pack2(a0.z, a0.w);
            ap[2] = pack2(a1.x, a1.y);
            ap[3] = pack2(a1.z, a1.w);

            float br[TN_];
            if constexpr (TN_ == 8) {
                float4 b0 = *(const float4*)&Bs[buf][kk][tcx * 4];
                float4 b1 = *(const float4*)&Bs[buf][kk][tcx * 4 + 64];
                br[0] = b0.x; br[1] = b0.y; br[2] = b0.z; br[3] = b0.w;
                br[4] = b1.x; br[5] = b1.y; br[6] = b1.z; br[7] = b1.w;
            } else if constexpr (TN_ == 4) {
                float4 b0 = *(const float4*)&Bs[buf][kk][tcx * 4];
                br[0] = b0.x; br[1] = b0.y; br[2] = b0.z; br[3] = b0.w;
            } else if constexpr (TN_ == 2) {
                float2 b0 = *(const float2*)&Bs[buf][kk][tcx * 2];
                br[0] = b0.x; br[1] = b0.y;
            } else {
                br[0] = Bs[buf][kk][tcx];
            }
            unsigned long long bd[TN_];
#pragma unroll
            for (int n = 0; n < TN_; n++) bd[n] = pack2(br[n], br[n]);
#pragma unroll
            for (int j = 0; j < 4; j++)
#pragma unroll
                for (int n = 0; n < TN_; n++)
                    ffma2(accp[j][n], ap[j], bd[n]);
        }
        if (kt + 1 < KTILES) {
            const int nb = buf ^ 1;
            As[nb][acol + 0][arow] = av.x;
            As[nb][acol + 1][arow] = av.y;
            As[nb][acol + 2][arow] = av.z;
            As[nb][acol + 3][arow] = av.w;
            if (tid < BLOADERS) *(float4*)&Bs[nb][brow][bcol] = bv;
        }
        __syncthreads();
    }

    float acc[8][TN_];
#pragma unroll
    for (int j = 0; j < 4; j++)
#pragma unroll
        for (int n = 0; n < TN_; n++)
            unpack2(accp[j][n], acc[2 * j][n], acc[2 * j + 1][n]);

    float bb[TN_];
    if constexpr (TN_ == 8) {
        float4 t0 = *(const float4*)&bias[tcx * 4];
        float4 t1 = *(const float4*)&bias[tcx * 4 + 64];
        bb[0]=t0.x; bb[1]=t0.y; bb[2]=t0.z; bb[3]=t0.w;
        bb[4]=t1.x; bb[5]=t1.y; bb[6]=t1.z; bb[7]=t1.w;
    } else if constexpr (TN_ == 4) {
        float4 t0 = *(const float4*)&bias[tcx * 4];
        bb[0]=t0.x; bb[1]=t0.y; bb[2]=t0.z; bb[3]=t0.w;
    } else if constexpr (TN_ == 2) {
        float2 t0 = *(const float2*)&bias[tcx * 2];
        bb[0]=t0.x; bb[1]=t0.y;
    } else {
        bb[0] = bias[tcx];
    }

#pragma unroll
    for (int g = 0; g < 2; g++) {
#pragma unroll
        for (int m = 0; m < 4; m++) {
            int px = px0 + tcy * 4 + m + g * 64;
            float* yr = Y + (size_t)px * BN_;
            float ov[TN_];
#pragma unroll
            for (int n = 0; n < TN_; n++) ov[n] = mish(acc[g * 4 + m][n] + bb[n]);
            if constexpr (TN_ == 8) {
                *(float4*)&yr[tcx * 4]      = make_float4(ov[0], ov[1], ov[2], ov[3]);
                *(float4*)&yr[tcx * 4 + 64] = make_float4(ov[4], ov[5], ov[6], ov[7]);
            } else if constexpr (TN_ == 4) {
                *(float4*)&yr[tcx * 4] = make_float4(ov[0], ov[1], ov[2], ov[3]);
            } else if constexpr (TN_ == 2) {
                *(float2*)&yr[tcx * 2] = make_float2(ov[0], ov[1]);
            } else {
                yr[tcx] = ov[0];
            }
        }
    }
}

// ---------------- kernel 4: BN + 3x3 flow conv + scale ----------------
__global__ void final_kernel(const float* __restrict__ X,
                             const float* __restrict__ gamma, const float* __restrict__ beta,
                             const float* __restrict__ mean,  const float* __restrict__ var,
                             const float* __restrict__ Wf, float* __restrict__ out)
{
    int pix = blockIdx.x * blockDim.x + threadIdx.x;
    if (pix >= NPIX) return;
    int w = pix % Wn;
    int h = (pix / Wn) % Hn;
    int b = pix / (Wn * Hn);

    float sc[16], sh[16];
#pragma unroll
    for (int c = 0; c < 16; c++) {
        float s = gamma[c] * rsqrtf(var[c] + BN_EPS);
        sc[c] = s;
        sh[c] = beta[c] - mean[c] * s;
    }

    float f0 = 0.f, f1 = 0.f;
#pragma unroll
    for (int ky = 0; ky < 3; ky++) {
        int hh = h + ky - 1;
        if (hh < 0 || hh >= Hn) continue;
#pragma unroll
        for (int kx = 0; kx < 3; kx++) {
            int ww = w + kx - 1;
            if (ww < 0 || ww >= Wn) continue;
            const float* xr = X + ((size_t)((b * Hn + hh) * Wn + ww)) * 16;
            const float* wr = Wf + (ky * 3 + kx) * 16 * 2;
#pragma unroll
            for (int c = 0; c < 16; c++) {
                float xv = xr[c] * sc[c] + sh[c];
                f0 += xv * wr[c * 2 + 0];
                f1 += xv * wr[c * 2 + 1];
            }
        }
    }
    out[(size_t)pix * 2 + 0] = FLOW_SCALE * f0;
    out[(size_t)pix * 2 + 1] = FLOW_SCALE * f1;
}

// ---------------- launch ----------------
extern "C" void kernel_launch(void* const* d_in, const int* in_sizes, int n_in,
                              void* d_out, int out_size)
{
    const float* prv   = (const float*)d_in[0];
    const float* nxt   = (const float*)d_in[1];
    const float* dw0   = (const float*)d_in[2];
    const float* pw0   = (const float*)d_in[3];
    const float* b0    = (const float*)d_in[4];
    const float* dw1   = (const float*)d_in[5];
    const float* pw1   = (const float*)d_in[6];
    const float* b1    = (const float*)d_in[7];
    const float* dw2   = (const float*)d_in[8];
    const float* pw2   = (const float*)d_in[9];
    const float* b2    = (const float*)d_in[10];
    const float* dw3   = (const float*)d_in[11];
    const float* pw3   = (const float*)d_in[12];
    const float* b3    = (const float*)d_in[13];
    const float* bng   = (const float*)d_in[14];
    const float* bnb   = (const float*)d_in[15];
    const float* bnm   = (const float*)d_in[16];
    const float* bnv   = (const float*)d_in[17];
    const float* flw   = (const float*)d_in[18];
    float* out = (float*)d_out;

    float *A = nullptr, *Bb = nullptr, *W0 = nullptr, *PW0 = nullptr;
    cudaGetSymbolAddress((void**)&A,   g_bufA);
    cudaGetSymbolAddress((void**)&Bb,  g_bufB);
    cudaGetSymbolAddress((void**)&W0,  g_dw0pad);
    cudaGetSymbolAddress((void**)&PW0, g_pw0pad);

    pad_w_kernel<<<(P0 * 128 + 255) / 256, 256>>>(dw0, pw0);

    // cost volume + concat -> A [NPIX, 216]
    {
        dim3 grid(Wn / 32, Hn / 8, Bn);
        cost_kernel<0, 5><<<grid, 128>>>(prv, nxt, A);
        cost_kernel<5, 4><<<grid, 128>>>(prv, nxt, A);
    }

    // layer 0
    dw4y_kernel<54, P0, P0><<<((NPIX / 4) * 54 + 255) / 256, 256>>>(A, W0, Bb);
    sgemm_mish<128, 8, P0 / 8><<<NPIX / 128, 256>>>(Bb, P0, PW0, b0, A);
    // layer 1
    dw4y_kernel<32, 128, 128><<<((NPIX / 4) * 32 + 255) / 256, 256>>>(A, dw1, Bb);
    sgemm_mish<64, 4, 16><<<NPIX / 128, 256>>>(Bb, 128, pw1, b1, A);
    // layer 2
    dw4y_kernel<16, 64, 64><<<((NPIX / 4) * 16 + 255) / 256, 256>>>(A, dw2, Bb);
    sgemm_mish<32, 2, 8><<<NPIX / 128, 256>>>(Bb, 64, pw2, b2, A);
    // layer 3
    dw4y_kernel<8, 32, 32><<<((NPIX / 4) * 8 + 255) / 256, 256>>>(A, dw3, Bb);
    sgemm_mish<16, 1, 4><<<NPIX / 128, 256>>>(Bb, 32, pw3, b3, A);

    final_kernel<<<(NPIX + 127) / 128, 128>>>(A, bng, bnb, bnm, bnv, flw, out);
}